// round 16
// baseline (speedup 1.0000x reference)
#include <cuda_runtime.h>
#include <cuda_fp16.h>
#include <cstdint>
#include <math.h>

#define S_LEN   2048
#define DHEAD   128
#define NHEADS  64        // B*H = 4*16
#define BM      256
#define BN      64
#define NT      (S_LEN / BN)     // 32
#define NSPLIT  2
#define TPS     (NT / NSPLIT)    // 16 tiles per split
#define THREADS 512              // 16 warps, 16 Q-rows each
#define NQB     (S_LEN / BM)     // 8 q-blocks

#define TILEB   49152            // one packed KV tile: khi 16K | klo 16K | v 16K

// smem layout (bytes): swizzled 256B rows
#define SM_QHI  0
#define SM_QLO  65536
#define SM_B0   131072           // [khi|klo|v] buffer 0
#define SM_B1   180224           // [khi|klo|v] buffer 1
#define SM_MBAR 229376           // full0, full1, empty0, empty1 (8B each)
#define SM_FLAG 229408           // 4B ticket-result broadcast
#define SM_TOT  229424

// (1/0.32) * log2(e), folded into Q at load
#define SFACT   4.5084219932497354f

// swizzled byte offset: row (256B each), ch = 16B chunk index 0..15
#define SWZ(row, ch) ((uint32_t)(row) * 256u + (uint32_t)((((ch) ^ ((row) & 7)) << 4)))

// pre-converted, pre-swizzled, tile-packed KV + split-KV partials (global scratch)
static __device__ __align__(16) uint8_t g_kv[(size_t)NHEADS * NT * TILEB];
static __device__ __half g_po [NSPLIT * NHEADS * S_LEN * DHEAD];   // unnormalized partial O
static __device__ float  g_pm [NSPLIT * NHEADS * S_LEN];           // partial row max (log2)
static __device__ float  g_pl [NSPLIT * NHEADS * S_LEN];           // partial row sum
static __device__ int    g_tick[NHEADS * NQB];                     // split-pair tickets

static __device__ __forceinline__ float ex2f(float x) {
    float r; asm("ex2.approx.f32 %0, %1;" : "=f"(r) : "f"(x)); return r;
}
static __device__ __forceinline__ uint32_t h2exp(uint32_t x) {
    uint32_t r; asm("ex2.approx.f16x2 %0, %1;" : "=r"(r) : "r"(x)); return r;
}
static __device__ __forceinline__ uint32_t pack_h2(float a, float b) {
    __half2 h = __floats2half2_rn(a, b);
    return *reinterpret_cast<uint32_t*>(&h);
}
static __device__ __forceinline__ void ldsm4(uint32_t* r, uint32_t a) {
    asm volatile("ldmatrix.sync.aligned.m8n8.x4.shared.b16 {%0,%1,%2,%3}, [%4];"
                 : "=r"(r[0]), "=r"(r[1]), "=r"(r[2]), "=r"(r[3]) : "r"(a));
}
static __device__ __forceinline__ void ldsm4t(uint32_t* r, uint32_t a) {
    asm volatile("ldmatrix.sync.aligned.m8n8.x4.trans.shared.b16 {%0,%1,%2,%3}, [%4];"
                 : "=r"(r[0]), "=r"(r[1]), "=r"(r[2]), "=r"(r[3]) : "r"(a));
}
static __device__ __forceinline__ void mma_f16(float* d, const uint32_t* a, const uint32_t* b) {
    asm volatile(
        "mma.sync.aligned.m16n8k16.row.col.f32.f16.f16.f32 "
        "{%0,%1,%2,%3}, {%4,%5,%6,%7}, {%8,%9}, {%0,%1,%2,%3};\n"
        : "+f"(d[0]), "+f"(d[1]), "+f"(d[2]), "+f"(d[3])
        : "r"(a[0]), "r"(a[1]), "r"(a[2]), "r"(a[3]), "r"(b[0]), "r"(b[1]));
}
static __device__ __forceinline__ void split8(const float* x, uint4& uh, uint4& ul) {
    uint32_t h[4], l[4];
    #pragma unroll
    for (int j = 0; j < 4; ++j) {
        float a = x[2 * j], b = x[2 * j + 1];
        __half ha = __float2half_rn(a), hb = __float2half_rn(b);
        h[j] = pack_h2(__half2float(ha), __half2float(hb));
        l[j] = pack_h2(a - __half2float(ha), b - __half2float(hb));
    }
    uh = make_uint4(h[0], h[1], h[2], h[3]);
    ul = make_uint4(l[0], l[1], l[2], l[3]);
}
static __device__ __forceinline__ uint4 pack8h(const float* x) {
    return make_uint4(pack_h2(x[0], x[1]), pack_h2(x[2], x[3]),
                      pack_h2(x[4], x[5]), pack_h2(x[6], x[7]));
}
static __device__ __forceinline__ void mbar_init(uint32_t mbar, uint32_t cnt) {
    asm volatile("mbarrier.init.shared.b64 [%0], %1;" :: "r"(mbar), "r"(cnt) : "memory");
}
static __device__ __forceinline__ void mbar_expect(uint32_t mbar, uint32_t bytes) {
    asm volatile("mbarrier.arrive.expect_tx.shared.b64 _, [%0], %1;"
                 :: "r"(mbar), "r"(bytes) : "memory");
}
static __device__ __forceinline__ void mbar_arrive(uint32_t mbar) {
    asm volatile("mbarrier.arrive.shared.b64 _, [%0];" :: "r"(mbar) : "memory");
}
static __device__ __forceinline__ void bulk_cp(uint32_t dst, const void* src, uint32_t bytes,
                                               uint32_t mbar) {
    asm volatile(
        "cp.async.bulk.shared::cluster.global.mbarrier::complete_tx::bytes [%0], [%1], %2, [%3];"
        :: "r"(dst), "l"(src), "r"(bytes), "r"(mbar) : "memory");
}
static __device__ __forceinline__ void mbar_wait(uint32_t mbar, uint32_t parity) {
    asm volatile(
        "{\n\t.reg .pred P1;\n\t"
        "WAIT_LOOP_%=:\n\t"
        "mbarrier.try_wait.parity.acquire.cta.shared::cta.b64 P1, [%0], %1, 0x989680;\n\t"
        "@P1 bra.uni WAIT_DONE_%=;\n\t"
        "bra.uni WAIT_LOOP_%=;\n\t"
        "WAIT_DONE_%=:\n\t}"
        :: "r"(mbar), "r"(parity) : "memory");
}

// ---- pre-pass: K -> hi/lo fp16 planes, V -> fp16, pre-swizzled tile-packed ----
__global__ __launch_bounds__(256)
void conv_kv_kernel(const float* __restrict__ K, const float* __restrict__ V) {
    // reset ALL split-pair tickets for this launch (strided: 512 entries, 256 threads)
    if (blockIdx.x == 0) {
        for (int t = threadIdx.x; t < NHEADS * NQB; t += 256) g_tick[t] = 0;
    }

    const int64_t nchunk = (int64_t)NHEADS * S_LEN * (DHEAD / 8);
    int64_t idx = (int64_t)blockIdx.x * blockDim.x + threadIdx.x;
    if (idx >= nchunk) return;
    int64_t row = idx >> 4;               // head*S_LEN + s
    int     ch  = (int)(idx & 15);
    int64_t h   = row / S_LEN;
    int     s   = (int)(row - h * S_LEN);
    int     tile = s / BN, rl = s % BN;
    uint8_t* base = g_kv + ((size_t)h * NT + tile) * TILEB;
    uint32_t off = SWZ(rl, ch);

    const float* ks = K + idx * 8;
    const float* vs = V + idx * 8;
    float4 t0 = *(const float4*)ks;
    float4 t1 = *(const float4*)(ks + 4);
    float kf[8] = {t0.x,t0.y,t0.z,t0.w,t1.x,t1.y,t1.z,t1.w};
    float4 u0 = *(const float4*)vs;
    float4 u1 = *(const float4*)(vs + 4);
    float vf[8] = {u0.x,u0.y,u0.z,u0.w,u1.x,u1.y,u1.z,u1.w};
    uint4 uh, ul; split8(kf, uh, ul);
    *(uint4*)(base + off)         = uh;
    *(uint4*)(base + 16384 + off) = ul;
    *(uint4*)(base + 32768 + off) = pack8h(vf);
}

__global__ __launch_bounds__(THREADS, 1)
void fa_db_kernel(const float* __restrict__ Q, float* __restrict__ O) {
    extern __shared__ __align__(16) char sm[];
    const uint32_t smb = (uint32_t)__cvta_generic_to_shared(sm);

    const int tid  = threadIdx.x;
    const int warp = tid >> 5;
    const int lane = tid & 31;
    const int g    = lane >> 2;
    const int c    = lane & 3;
    const uint32_t rl = lane & 7;

    const int bh    = blockIdx.y;
    const int split = blockIdx.z;
    const int q0 = blockIdx.x * BM;
    const size_t head = (size_t)bh * S_LEN * DHEAD;
    const int rbase = warp * 16;

    const uint8_t* kvhead = g_kv + ((size_t)bh * NT + split * TPS) * TILEB;

    const uint32_t FULL0  = smb + SM_MBAR;
    const uint32_t FULL1  = smb + SM_MBAR + 8;
    const uint32_t EMPTY0 = smb + SM_MBAR + 16;
    const uint32_t EMPTY1 = smb + SM_MBAR + 24;

    // ---- mbarrier init: full (count 1, tx-driven), empty (count 16 = warps) ----
    if (tid == 0) {
        mbar_init(FULL0, 1);
        mbar_init(FULL1, 1);
        mbar_init(EMPTY0, 16);
        mbar_init(EMPTY1, 16);
    }
    __syncthreads();   // mbarriers visible before first bulk targets them

    // ---- prefetch both buffers immediately (overlaps Q-convert prologue) ----
    if (tid == 0) {
        mbar_expect(FULL0, TILEB);
        bulk_cp(smb + SM_B0, kvhead, TILEB, FULL0);
        mbar_expect(FULL1, TILEB);
        bulk_cp(smb + SM_B1, kvhead + TILEB, TILEB, FULL1);
    }

    // ---- load Q tile: scale, split hi/lo fp16, swizzled store ----
    for (int i = tid; i < BM * 16; i += THREADS) {
        int row = i >> 4, ch = i & 15;
        const float* src = Q + head + (size_t)(q0 + row) * DHEAD + ch * 8;
        float4 f0 = *(const float4*)src;
        float4 f1 = *(const float4*)(src + 4);
        float f[8] = {f0.x*SFACT, f0.y*SFACT, f0.z*SFACT, f0.w*SFACT,
                      f1.x*SFACT, f1.y*SFACT, f1.z*SFACT, f1.w*SFACT};
        uint4 uh, ul; split8(f, uh, ul);
        uint32_t off = SWZ(row, ch);
        *(uint4*)(sm + SM_QHI + off) = uh;
        *(uint4*)(sm + SM_QLO + off) = ul;
    }
    __syncthreads();   // Q visible to all warps before tile 0 compute

    // ---- per-lane fragment row offsets ----
    const uint32_t qrow = (uint32_t)(rbase + (lane & 15)) * 256u;
    const uint32_t chA0 = lane >> 4;
    const uint32_t krow = (uint32_t)((lane & 7) + ((lane >> 4) << 3)) * 256u;
    const uint32_t chB0 = (lane >> 3) & 1;
    const uint32_t vrow = (uint32_t)((lane & 7) + (((lane >> 3) & 1) << 3)) * 256u;
    const uint32_t chV0 = lane >> 4;

    const uint32_t qA_h = smb + SM_QHI + qrow;
    const uint32_t qA_l = smb + SM_QLO + qrow;

    float o[16][4];
    #pragma unroll
    for (int i = 0; i < 16; i++) { o[i][0]=0.f; o[i][1]=0.f; o[i][2]=0.f; o[i][3]=0.f; }
    float m0 = -INFINITY, m1 = -INFINITY, l0 = 0.f, l1 = 0.f;
    int fph0 = 0, fph1 = 0;   // full-barrier phase per buffer (all threads)
    int eph0 = 0, eph1 = 0;   // empty-barrier phase per buffer (thread 0)

    for (int jtl = 0; jtl < TPS; ++jtl) {
        const int buf = jtl & 1;
        if (buf == 0) { mbar_wait(FULL0, (uint32_t)fph0); fph0 ^= 1; }
        else          { mbar_wait(FULL1, (uint32_t)fph1); fph1 ^= 1; }

        const uint32_t bb = smb + (buf ? SM_B1 : SM_B0);
        const uint32_t kB_h = bb + krow;
        const uint32_t kB_l = bb + 16384u + krow;
        const uint32_t vB   = bb + 32768u + vrow;

        // ---- S = Q K^T : 3x fp16 split (hh, lh, hl) ----
        float s[8][4];
        #pragma unroll
        for (int i = 0; i < 8; i++) { s[i][0]=0.f; s[i][1]=0.f; s[i][2]=0.f; s[i][3]=0.f; }

        #pragma unroll 2
        for (int kk = 0; kk < 8; ++kk) {
            const uint32_t offA = ((chA0 + 2 * kk) ^ rl) << 4;
            uint32_t aH[4], aL[4];
            ldsm4(aH, qA_h + offA);
            ldsm4(aL, qA_l + offA);
            const uint32_t offB = ((chB0 + 2 * kk) ^ rl) << 4;
            #pragma unroll
            for (int hfl = 0; hfl < 2; ++hfl) {
                const uint32_t bbase = (uint32_t)hfl * 8192u + offB;
                uint32_t bhf[8], blf[8];
                ldsm4(&bhf[0], kB_h + bbase);
                ldsm4(&bhf[4], kB_h + bbase + 4096u);
                ldsm4(&blf[0], kB_l + bbase);
                ldsm4(&blf[4], kB_l + bbase + 4096u);
                float (*sp)[4] = &s[hfl * 4];
                #pragma unroll
                for (int j = 0; j < 4; ++j) mma_f16(sp[j], aH, &bhf[j * 2]);
                #pragma unroll
                for (int j = 0; j < 4; ++j) mma_f16(sp[j], aL, &bhf[j * 2]);
                #pragma unroll
                for (int j = 0; j < 4; ++j) mma_f16(sp[j], aH, &blf[j * 2]);
            }
        }

        // ---- online softmax (base-2 domain; scale folded into Q) ----
        float mx0 = -INFINITY, mx1 = -INFINITY;
        #pragma unroll
        for (int ng = 0; ng < 8; ++ng) {
            mx0 = fmaxf(mx0, fmaxf(s[ng][0], s[ng][1]));
            mx1 = fmaxf(mx1, fmaxf(s[ng][2], s[ng][3]));
        }
        mx0 = fmaxf(mx0, __shfl_xor_sync(0xffffffffu, mx0, 1));
        mx0 = fmaxf(mx0, __shfl_xor_sync(0xffffffffu, mx0, 2));
        mx1 = fmaxf(mx1, __shfl_xor_sync(0xffffffffu, mx1, 1));
        mx1 = fmaxf(mx1, __shfl_xor_sync(0xffffffffu, mx1, 2));

        float m0n = fmaxf(m0, mx0), m1n = fmaxf(m1, mx1);
        float al0 = ex2f(m0 - m0n), al1 = ex2f(m1 - m1n);

        // exp in f16x2: packed (s - mn) -> ex2 -> P fragments directly
        uint32_t p0[8], p1[8];
        float sum0 = 0.f, sum1 = 0.f;
        #pragma unroll
        for (int ng = 0; ng < 8; ++ng) {
            p0[ng] = h2exp(pack_h2(s[ng][0] - m0n, s[ng][1] - m0n));
            p1[ng] = h2exp(pack_h2(s[ng][2] - m1n, s[ng][3] - m1n));
            float2 f0 = __half22float2(*(__half2*)&p0[ng]);
            float2 f1 = __half22float2(*(__half2*)&p1[ng]);
            sum0 += f0.x + f0.y;
            sum1 += f1.x + f1.y;
        }
        sum0 += __shfl_xor_sync(0xffffffffu, sum0, 1);
        sum0 += __shfl_xor_sync(0xffffffffu, sum0, 2);
        sum1 += __shfl_xor_sync(0xffffffffu, sum1, 1);
        sum1 += __shfl_xor_sync(0xffffffffu, sum1, 2);
        l0 = l0 * al0 + sum0;
        l1 = l1 * al1 + sum1;
        m0 = m0n; m1 = m1n;

        // rescale O only if any lane's max moved (alpha != 1)
        if (!__all_sync(0xffffffffu, (al0 == 1.0f) && (al1 == 1.0f))) {
            #pragma unroll
            for (int nf = 0; nf < 16; ++nf) {
                o[nf][0] *= al0; o[nf][1] *= al0; o[nf][2] *= al1; o[nf][3] *= al1;
            }
        }

        // ---- O += P V : P fragments already in registers (fp16) ----
        #pragma unroll
        for (int k2 = 0; k2 < 4; ++k2) {
            uint32_t pa[4];
            pa[0] = p0[2 * k2];
            pa[1] = p1[2 * k2];
            pa[2] = p0[2 * k2 + 1];
            pa[3] = p1[2 * k2 + 1];
            #pragma unroll
            for (int nfp = 0; nfp < 8; ++nfp) {
                const uint32_t offV = ((chV0 + 2 * nfp) ^ rl) << 4;
                uint32_t bv[4];
                ldsm4t(bv, vB + (uint32_t)k2 * 4096u + offV);
                mma_f16(o[2 * nfp],     pa, bv);
                mma_f16(o[2 * nfp + 1], pa, bv + 2);
            }
        }

        // ---- done reading this buffer: warp-elected release (ldmatrix is warp-sync) ----
        if (lane == 0) mbar_arrive(buf == 0 ? EMPTY0 : EMPTY1);

        // ---- producer: refill this buffer with tile jtl+2 once fully released ----
        if (tid == 0 && jtl + 2 < TPS) {
            if (buf == 0) {
                mbar_wait(EMPTY0, (uint32_t)eph0); eph0 ^= 1;
                mbar_expect(FULL0, TILEB);
                bulk_cp(smb + SM_B0, kvhead + (size_t)(jtl + 2) * TILEB, TILEB, FULL0);
            } else {
                mbar_wait(EMPTY1, (uint32_t)eph1); eph1 ^= 1;
                mbar_expect(FULL1, TILEB);
                bulk_cp(smb + SM_B1, kvhead + (size_t)(jtl + 2) * TILEB, TILEB, FULL1);
            }
        }
    }

    // ---- epilogue 1: write unnormalized fp16 partials + (m, l) ----
    const size_t prow = ((size_t)split * NHEADS + bh) * S_LEN + q0 + rbase;
    if (c == 0) {
        g_pm[prow + g]     = m0;  g_pl[prow + g]     = l0;
        g_pm[prow + g + 8] = m1;  g_pl[prow + g + 8] = l1;
    }
    __half* po = g_po + prow * DHEAD;
    #pragma unroll
    for (int nf = 0; nf < 16; ++nf) {
        *(uint32_t*)(po + (size_t)(g)     * DHEAD + nf * 8 + c * 2) = pack_h2(o[nf][0], o[nf][1]);
        *(uint32_t*)(po + (size_t)(g + 8) * DHEAD + nf * 8 + c * 2) = pack_h2(o[nf][2], o[nf][3]);
    }

    // ---- epilogue 2: ticket — odd finisher of the split pair merges ----
    // (each launch adds exactly 2 per ticket; the second finisher always sees
    //  an ODD value regardless of the ticket's starting value -> replay-safe)
    __threadfence();
    __syncthreads();
    int* flag = (int*)(sm + SM_FLAG);
    if (tid == 0) *flag = atomicAdd(&g_tick[bh * NQB + blockIdx.x], 1);
    __syncthreads();
    if (*flag & 1) {
        __threadfence();   // acquire partner's partials
        const size_t rows = (size_t)NHEADS * S_LEN;
        // merge this CTA's BM rows: fixed split-index order -> deterministic
        for (int i = tid; i < BM * (DHEAD / 4); i += THREADS) {
            int rloc = i >> 5;            // row within block
            int qg   = i & 31;            // 4-col group
            size_t r0 = (size_t)bh * S_LEN + q0 + rloc;      // split-0 row index
            float pm0 = g_pm[r0], pm1 = g_pm[rows + r0];
            float pl0 = g_pl[r0], pl1 = g_pl[rows + r0];
            float mM = fmaxf(pm0, pm1);
            float w0 = ex2f(pm0 - mM), w1 = ex2f(pm1 - mM);
            float inv = 1.f / (w0 * pl0 + w1 * pl1);
            uint2 a = *(const uint2*)(g_po + r0 * DHEAD + qg * 4);
            uint2 b = *(const uint2*)(g_po + (rows + r0) * DHEAD + qg * 4);
            __half2 a0 = *(__half2*)&a.x, a1 = *(__half2*)&a.y;
            __half2 b0 = *(__half2*)&b.x, b1 = *(__half2*)&b.y;
            float4 out;
            out.x = (w0 * __low2float(a0)  + w1 * __low2float(b0))  * inv;
            out.y = (w0 * __high2float(a0) + w1 * __high2float(b0)) * inv;
            out.z = (w0 * __low2float(a1)  + w1 * __low2float(b1))  * inv;
            out.w = (w0 * __high2float(a1) + w1 * __high2float(b1)) * inv;
            *(float4*)(O + r0 * DHEAD + qg * 4) = out;
        }
    }
}

extern "C" void kernel_launch(void* const* d_in, const int* in_sizes, int n_in,
                              void* d_out, int out_size) {
    const float* q = (const float*)d_in[0];
    const float* k = (const float*)d_in[1];
    const float* v = (const float*)d_in[2];
    float* o = (float*)d_out;

    const int64_t nchunk = (int64_t)NHEADS * S_LEN * (DHEAD / 8);
    conv_kv_kernel<<<(int)((nchunk + 255) / 256), 256>>>(k, v);

    cudaFuncSetAttribute(fa_db_kernel, cudaFuncAttributeMaxDynamicSharedMemorySize, SM_TOT);
    dim3 grid(NQB, NHEADS, NSPLIT);
    fa_db_kernel<<<grid, THREADS, SM_TOT>>>(q, o);
}

// round 17
// speedup vs baseline: 1.0698x; 1.0698x over previous
#include <cuda_runtime.h>
#include <cuda_fp16.h>
#include <cstdint>
#include <math.h>

#define S_LEN   2048
#define DHEAD   128
#define NHEADS  64        // B*H = 4*16
#define BM      256
#define BN      64
#define NT      (S_LEN / BN)     // 32
#define NSPLIT  2
#define TPS     (NT / NSPLIT)    // 16 tiles per split
#define THREADS 512              // 16 warps, 16 Q-rows each

#define TILEB   49152            // one packed KV tile: khi 16K | klo 16K | v 16K

// smem layout (bytes): swizzled 256B rows
#define SM_QHI  0
#define SM_QLO  65536
#define SM_B0   131072           // [khi|klo|v] buffer 0
#define SM_B1   180224           // [khi|klo|v] buffer 1
#define SM_MBAR 229376           // full0, full1, empty0, empty1 (8B each)
#define SM_TOT  229440

// (1/0.32) * log2(e), folded into Q at load
#define SFACT   4.5084219932497354f

// swizzled byte offset: row (256B each), ch = 16B chunk index 0..15
#define SWZ(row, ch) ((uint32_t)(row) * 256u + (uint32_t)((((ch) ^ ((row) & 7)) << 4)))

// pre-converted, pre-swizzled, tile-packed KV + split-KV partials (global scratch)
static __device__ __align__(16) uint8_t g_kv[(size_t)NHEADS * NT * TILEB];
static __device__ __half g_po [NSPLIT * NHEADS * S_LEN * DHEAD];   // unnormalized partial O
static __device__ float  g_pm [NSPLIT * NHEADS * S_LEN];           // partial row max (log2)
static __device__ float  g_pl [NSPLIT * NHEADS * S_LEN];           // partial row sum

static __device__ __forceinline__ float ex2f(float x) {
    float r; asm("ex2.approx.f32 %0, %1;" : "=f"(r) : "f"(x)); return r;
}
static __device__ __forceinline__ uint32_t h2exp(uint32_t x) {
    uint32_t r; asm("ex2.approx.f16x2 %0, %1;" : "=r"(r) : "r"(x)); return r;
}
static __device__ __forceinline__ uint32_t pack_h2(float a, float b) {
    __half2 h = __floats2half2_rn(a, b);
    return *reinterpret_cast<uint32_t*>(&h);
}
static __device__ __forceinline__ void ldsm4(uint32_t* r, uint32_t a) {
    asm volatile("ldmatrix.sync.aligned.m8n8.x4.shared.b16 {%0,%1,%2,%3}, [%4];"
                 : "=r"(r[0]), "=r"(r[1]), "=r"(r[2]), "=r"(r[3]) : "r"(a));
}
static __device__ __forceinline__ void ldsm4t(uint32_t* r, uint32_t a) {
    asm volatile("ldmatrix.sync.aligned.m8n8.x4.trans.shared.b16 {%0,%1,%2,%3}, [%4];"
                 : "=r"(r[0]), "=r"(r[1]), "=r"(r[2]), "=r"(r[3]) : "r"(a));
}
static __device__ __forceinline__ void mma_f16(float* d, const uint32_t* a, const uint32_t* b) {
    asm volatile(
        "mma.sync.aligned.m16n8k16.row.col.f32.f16.f16.f32 "
        "{%0,%1,%2,%3}, {%4,%5,%6,%7}, {%8,%9}, {%0,%1,%2,%3};\n"
        : "+f"(d[0]), "+f"(d[1]), "+f"(d[2]), "+f"(d[3])
        : "r"(a[0]), "r"(a[1]), "r"(a[2]), "r"(a[3]), "r"(b[0]), "r"(b[1]));
}
static __device__ __forceinline__ void split8(const float* x, uint4& uh, uint4& ul) {
    uint32_t h[4], l[4];
    #pragma unroll
    for (int j = 0; j < 4; ++j) {
        float a = x[2 * j], b = x[2 * j + 1];
        __half ha = __float2half_rn(a), hb = __float2half_rn(b);
        h[j] = pack_h2(__half2float(ha), __half2float(hb));
        l[j] = pack_h2(a - __half2float(ha), b - __half2float(hb));
    }
    uh = make_uint4(h[0], h[1], h[2], h[3]);
    ul = make_uint4(l[0], l[1], l[2], l[3]);
}
static __device__ __forceinline__ uint4 pack8h(const float* x) {
    return make_uint4(pack_h2(x[0], x[1]), pack_h2(x[2], x[3]),
                      pack_h2(x[4], x[5]), pack_h2(x[6], x[7]));
}
static __device__ __forceinline__ void mbar_init(uint32_t mbar, uint32_t cnt) {
    asm volatile("mbarrier.init.shared.b64 [%0], %1;" :: "r"(mbar), "r"(cnt) : "memory");
}
static __device__ __forceinline__ void mbar_expect(uint32_t mbar, uint32_t bytes) {
    asm volatile("mbarrier.arrive.expect_tx.shared.b64 _, [%0], %1;"
                 :: "r"(mbar), "r"(bytes) : "memory");
}
static __device__ __forceinline__ void mbar_arrive(uint32_t mbar) {
    asm volatile("mbarrier.arrive.shared.b64 _, [%0];" :: "r"(mbar) : "memory");
}
static __device__ __forceinline__ void bulk_cp(uint32_t dst, const void* src, uint32_t bytes,
                                               uint32_t mbar) {
    asm volatile(
        "cp.async.bulk.shared::cluster.global.mbarrier::complete_tx::bytes [%0], [%1], %2, [%3];"
        :: "r"(dst), "l"(src), "r"(bytes), "r"(mbar) : "memory");
}
static __device__ __forceinline__ void mbar_wait(uint32_t mbar, uint32_t parity) {
    asm volatile(
        "{\n\t.reg .pred P1;\n\t"
        "WAIT_LOOP_%=:\n\t"
        "mbarrier.try_wait.parity.acquire.cta.shared::cta.b64 P1, [%0], %1, 0x989680;\n\t"
        "@P1 bra.uni WAIT_DONE_%=;\n\t"
        "bra.uni WAIT_LOOP_%=;\n\t"
        "WAIT_DONE_%=:\n\t}"
        :: "r"(mbar), "r"(parity) : "memory");
}

// ---- pre-pass: K -> hi/lo fp16 planes, V -> fp16, pre-swizzled tile-packed ----
__global__ __launch_bounds__(256)
void conv_kv_kernel(const float* __restrict__ K, const float* __restrict__ V) {
    const int64_t nchunk = (int64_t)NHEADS * S_LEN * (DHEAD / 8);
    int64_t idx = (int64_t)blockIdx.x * blockDim.x + threadIdx.x;
    if (idx >= nchunk) return;
    int64_t row = idx >> 4;               // head*S_LEN + s
    int     ch  = (int)(idx & 15);
    int64_t h   = row / S_LEN;
    int     s   = (int)(row - h * S_LEN);
    int     tile = s / BN, rl = s % BN;
    uint8_t* base = g_kv + ((size_t)h * NT + tile) * TILEB;
    uint32_t off = SWZ(rl, ch);

    const float* ks = K + idx * 8;
    const float* vs = V + idx * 8;
    float4 t0 = *(const float4*)ks;
    float4 t1 = *(const float4*)(ks + 4);
    float kf[8] = {t0.x,t0.y,t0.z,t0.w,t1.x,t1.y,t1.z,t1.w};
    float4 u0 = *(const float4*)vs;
    float4 u1 = *(const float4*)(vs + 4);
    float vf[8] = {u0.x,u0.y,u0.z,u0.w,u1.x,u1.y,u1.z,u1.w};
    uint4 uh, ul; split8(kf, uh, ul);
    *(uint4*)(base + off)         = uh;
    *(uint4*)(base + 16384 + off) = ul;
    *(uint4*)(base + 32768 + off) = pack8h(vf);
}

// ---- merge: combine NSPLIT partials into normalized O ----
__global__ __launch_bounds__(256)
void merge_kernel(float* __restrict__ O) {
    int64_t t = (int64_t)blockIdx.x * blockDim.x + threadIdx.x;
    const int64_t total = (int64_t)NHEADS * S_LEN * 32;
    if (t >= total) return;
    int64_t row = t >> 5;
    int     qg  = (int)(t & 31);
    const int64_t rows = (int64_t)NHEADS * S_LEN;
    float m0 = g_pm[row], m1 = g_pm[rows + row];
    float l0 = g_pl[row], l1 = g_pl[rows + row];
    float mM = fmaxf(m0, m1);
    float w0 = ex2f(m0 - mM), w1 = ex2f(m1 - mM);
    float inv = 1.f / (w0 * l0 + w1 * l1);
    const __half* p0 = g_po + row * DHEAD + qg * 4;
    const __half* p1 = g_po + (int64_t)rows * DHEAD + row * DHEAD + qg * 4;
    uint2 a = *(const uint2*)p0;
    uint2 b = *(const uint2*)p1;
    __half2 a0 = *(__half2*)&a.x, a1 = *(__half2*)&a.y;
    __half2 b0 = *(__half2*)&b.x, b1 = *(__half2*)&b.y;
    float4 out;
    out.x = (w0 * __low2float(a0)  + w1 * __low2float(b0))  * inv;
    out.y = (w0 * __high2float(a0) + w1 * __high2float(b0)) * inv;
    out.z = (w0 * __low2float(a1)  + w1 * __low2float(b1))  * inv;
    out.w = (w0 * __high2float(a1) + w1 * __high2float(b1)) * inv;
    *(float4*)(O + row * DHEAD + qg * 4) = out;
}

__global__ __launch_bounds__(THREADS, 1)
void fa_db_kernel(const float* __restrict__ Q) {
    extern __shared__ __align__(16) char sm[];
    const uint32_t smb = (uint32_t)__cvta_generic_to_shared(sm);

    const int tid  = threadIdx.x;
    const int warp = tid >> 5;
    const int lane = tid & 31;
    const int g    = lane >> 2;
    const int c    = lane & 3;
    const uint32_t rl = lane & 7;

    const int bh    = blockIdx.y;
    const int split = blockIdx.z;
    const int q0 = blockIdx.x * BM;
    const size_t head = (size_t)bh * S_LEN * DHEAD;
    const int rbase = warp * 16;

    const uint8_t* kvhead = g_kv + ((size_t)bh * NT + split * TPS) * TILEB;

    const uint32_t FULL0  = smb + SM_MBAR;
    const uint32_t FULL1  = smb + SM_MBAR + 8;
    const uint32_t EMPTY0 = smb + SM_MBAR + 16;
    const uint32_t EMPTY1 = smb + SM_MBAR + 24;

    // ---- mbarrier init: full (count 1, tx-driven), empty (count 16 = warps) ----
    if (tid == 0) {
        mbar_init(FULL0, 1);
        mbar_init(FULL1, 1);
        mbar_init(EMPTY0, 16);
        mbar_init(EMPTY1, 16);
    }
    __syncthreads();   // mbarriers visible before first bulk targets them

    // ---- prefetch both buffers immediately (overlaps Q-convert prologue) ----
    if (tid == 0) {
        mbar_expect(FULL0, TILEB);
        bulk_cp(smb + SM_B0, kvhead, TILEB, FULL0);
        mbar_expect(FULL1, TILEB);
        bulk_cp(smb + SM_B1, kvhead + TILEB, TILEB, FULL1);
    }

    // ---- load Q tile: scale, split hi/lo fp16, swizzled store ----
    for (int i = tid; i < BM * 16; i += THREADS) {
        int row = i >> 4, ch = i & 15;
        const float* src = Q + head + (size_t)(q0 + row) * DHEAD + ch * 8;
        float4 f0 = *(const float4*)src;
        float4 f1 = *(const float4*)(src + 4);
        float f[8] = {f0.x*SFACT, f0.y*SFACT, f0.z*SFACT, f0.w*SFACT,
                      f1.x*SFACT, f1.y*SFACT, f1.z*SFACT, f1.w*SFACT};
        uint4 uh, ul; split8(f, uh, ul);
        uint32_t off = SWZ(row, ch);
        *(uint4*)(sm + SM_QHI + off) = uh;
        *(uint4*)(sm + SM_QLO + off) = ul;
    }
    __syncthreads();   // Q visible to all warps before tile 0 compute

    // ---- per-lane fragment row offsets ----
    const uint32_t qrow = (uint32_t)(rbase + (lane & 15)) * 256u;
    const uint32_t chA0 = lane >> 4;
    const uint32_t krow = (uint32_t)((lane & 7) + ((lane >> 4) << 3)) * 256u;
    const uint32_t chB0 = (lane >> 3) & 1;
    const uint32_t vrow = (uint32_t)((lane & 7) + (((lane >> 3) & 1) << 3)) * 256u;
    const uint32_t chV0 = lane >> 4;

    const uint32_t qA_h = smb + SM_QHI + qrow;
    const uint32_t qA_l = smb + SM_QLO + qrow;

    float o[16][4];
    #pragma unroll
    for (int i = 0; i < 16; i++) { o[i][0]=0.f; o[i][1]=0.f; o[i][2]=0.f; o[i][3]=0.f; }
    float m0 = -INFINITY, m1 = -INFINITY;
    float l0 = 0.f, l1 = 0.f;           // lane-local partials; reduced once in epilogue
    int fph0 = 0, fph1 = 0;   // full-barrier phase per buffer (all threads)
    int eph0 = 0, eph1 = 0;   // empty-barrier phase per buffer (thread 0)

    for (int jtl = 0; jtl < TPS; ++jtl) {
        const int buf = jtl & 1;
        if (buf == 0) { mbar_wait(FULL0, (uint32_t)fph0); fph0 ^= 1; }
        else          { mbar_wait(FULL1, (uint32_t)fph1); fph1 ^= 1; }

        const uint32_t bb = smb + (buf ? SM_B1 : SM_B0);
        const uint32_t kB_h = bb + krow;
        const uint32_t kB_l = bb + 16384u + krow;
        const uint32_t vB   = bb + 32768u + vrow;

        // ---- S = Q K^T : 3x fp16 split (hh, lh, hl) ----
        float s[8][4];
        #pragma unroll
        for (int i = 0; i < 8; i++) { s[i][0]=0.f; s[i][1]=0.f; s[i][2]=0.f; s[i][3]=0.f; }

        #pragma unroll 2
        for (int kk = 0; kk < 8; ++kk) {
            const uint32_t offA = ((chA0 + 2 * kk) ^ rl) << 4;
            uint32_t aH[4], aL[4];
            ldsm4(aH, qA_h + offA);
            ldsm4(aL, qA_l + offA);
            const uint32_t offB = ((chB0 + 2 * kk) ^ rl) << 4;
            #pragma unroll
            for (int hfl = 0; hfl < 2; ++hfl) {
                const uint32_t bbase = (uint32_t)hfl * 8192u + offB;
                uint32_t bhf[8], blf[8];
                ldsm4(&bhf[0], kB_h + bbase);
                ldsm4(&bhf[4], kB_h + bbase + 4096u);
                ldsm4(&blf[0], kB_l + bbase);
                ldsm4(&blf[4], kB_l + bbase + 4096u);
                float (*sp)[4] = &s[hfl * 4];
                #pragma unroll
                for (int j = 0; j < 4; ++j) mma_f16(sp[j], aH, &bhf[j * 2]);
                #pragma unroll
                for (int j = 0; j < 4; ++j) mma_f16(sp[j], aL, &bhf[j * 2]);
                #pragma unroll
                for (int j = 0; j < 4; ++j) mma_f16(sp[j], aH, &blf[j * 2]);
            }
        }

        // ---- online softmax (base-2 domain; scale folded into Q) ----
        float mx0 = -INFINITY, mx1 = -INFINITY;
        #pragma unroll
        for (int ng = 0; ng < 8; ++ng) {
            mx0 = fmaxf(mx0, fmaxf(s[ng][0], s[ng][1]));
            mx1 = fmaxf(mx1, fmaxf(s[ng][2], s[ng][3]));
        }
        mx0 = fmaxf(mx0, __shfl_xor_sync(0xffffffffu, mx0, 1));
        mx0 = fmaxf(mx0, __shfl_xor_sync(0xffffffffu, mx0, 2));
        mx1 = fmaxf(mx1, __shfl_xor_sync(0xffffffffu, mx1, 1));
        mx1 = fmaxf(mx1, __shfl_xor_sync(0xffffffffu, mx1, 2));

        float m0n = fmaxf(m0, mx0), m1n = fmaxf(m1, mx1);
        float al0 = ex2f(m0 - m0n), al1 = ex2f(m1 - m1n);

        // exp in f16x2: packed (s - mn) -> ex2 -> P fragments directly
        uint32_t p0[8], p1[8];
        float sum0 = 0.f, sum1 = 0.f;
        #pragma unroll
        for (int ng = 0; ng < 8; ++ng) {
            p0[ng] = h2exp(pack_h2(s[ng][0] - m0n, s[ng][1] - m0n));
            p1[ng] = h2exp(pack_h2(s[ng][2] - m1n, s[ng][3] - m1n));
            float2 f0 = __half22float2(*(__half2*)&p0[ng]);
            float2 f1 = __half22float2(*(__half2*)&p1[ng]);
            sum0 += f0.x + f0.y;
            sum1 += f1.x + f1.y;
        }
        // deferred l-reduction: alpha is quad-uniform, so lane-local partials are exact
        l0 = l0 * al0 + sum0;
        l1 = l1 * al1 + sum1;
        m0 = m0n; m1 = m1n;

        // rescale O only if any lane's max moved (alpha != 1)
        if (!__all_sync(0xffffffffu, (al0 == 1.0f) && (al1 == 1.0f))) {
            #pragma unroll
            for (int nf = 0; nf < 16; ++nf) {
                o[nf][0] *= al0; o[nf][1] *= al0; o[nf][2] *= al1; o[nf][3] *= al1;
            }
        }

        // ---- O += P V : P fragments already in registers (fp16) ----
        #pragma unroll
        for (int k2 = 0; k2 < 4; ++k2) {
            uint32_t pa[4];
            pa[0] = p0[2 * k2];
            pa[1] = p1[2 * k2];
            pa[2] = p0[2 * k2 + 1];
            pa[3] = p1[2 * k2 + 1];
            #pragma unroll
            for (int nfp = 0; nfp < 8; ++nfp) {
                const uint32_t offV = ((chV0 + 2 * nfp) ^ rl) << 4;
                uint32_t bv[4];
                ldsm4t(bv, vB + (uint32_t)k2 * 4096u + offV);
                mma_f16(o[2 * nfp],     pa, bv);
                mma_f16(o[2 * nfp + 1], pa, bv + 2);
            }
        }

        // ---- done reading this buffer: warp-elected release (ldmatrix is warp-sync) ----
        if (lane == 0) mbar_arrive(buf == 0 ? EMPTY0 : EMPTY1);

        // ---- producer: refill this buffer with tile jtl+2 once fully released ----
        if (tid == 0 && jtl + 2 < TPS) {
            if (buf == 0) {
                mbar_wait(EMPTY0, (uint32_t)eph0); eph0 ^= 1;
                mbar_expect(FULL0, TILEB);
                bulk_cp(smb + SM_B0, kvhead + (size_t)(jtl + 2) * TILEB, TILEB, FULL0);
            } else {
                mbar_wait(EMPTY1, (uint32_t)eph1); eph1 ^= 1;
                mbar_expect(FULL1, TILEB);
                bulk_cp(smb + SM_B1, kvhead + (size_t)(jtl + 2) * TILEB, TILEB, FULL1);
            }
        }
    }

    // ---- epilogue: reduce l across the quad, write partials + (m, l) ----
    l0 += __shfl_xor_sync(0xffffffffu, l0, 1);
    l0 += __shfl_xor_sync(0xffffffffu, l0, 2);
    l1 += __shfl_xor_sync(0xffffffffu, l1, 1);
    l1 += __shfl_xor_sync(0xffffffffu, l1, 2);

    const size_t prow = ((size_t)split * NHEADS + bh) * S_LEN + q0 + rbase;
    if (c == 0) {
        g_pm[prow + g]     = m0;  g_pl[prow + g]     = l0;
        g_pm[prow + g + 8] = m1;  g_pl[prow + g + 8] = l1;
    }
    __half* po = g_po + prow * DHEAD;
    #pragma unroll
    for (int nf = 0; nf < 16; ++nf) {
        *(uint32_t*)(po + (size_t)(g)     * DHEAD + nf * 8 + c * 2) = pack_h2(o[nf][0], o[nf][1]);
        *(uint32_t*)(po + (size_t)(g + 8) * DHEAD + nf * 8 + c * 2) = pack_h2(o[nf][2], o[nf][3]);
    }
}

extern "C" void kernel_launch(void* const* d_in, const int* in_sizes, int n_in,
                              void* d_out, int out_size) {
    const float* q = (const float*)d_in[0];
    const float* k = (const float*)d_in[1];
    const float* v = (const float*)d_in[2];
    float* o = (float*)d_out;

    const int64_t nchunk = (int64_t)NHEADS * S_LEN * (DHEAD / 8);
    conv_kv_kernel<<<(int)((nchunk + 255) / 256), 256>>>(k, v);

    cudaFuncSetAttribute(fa_db_kernel, cudaFuncAttributeMaxDynamicSharedMemorySize, SM_TOT);
    dim3 grid(S_LEN / BM, NHEADS, NSPLIT);
    fa_db_kernel<<<grid, THREADS, SM_TOT>>>(q);

    const int64_t mt = (int64_t)NHEADS * S_LEN * 32;
    merge_kernel<<<(int)((mt + 255) / 256), 256>>>(o);
}